// round 3
// baseline (speedup 1.0000x reference)
#include <cuda_runtime.h>
#include <math.h>

// Problem constants
#define M_TOK 16384      // BATCH * L
#define D_IN  1024
#define NF    356        // 256 (B) + 4 (X) + 64 (decay) + 32 (theta)
#define NFP   384        // padded feature count
#define NRF   256        // N * R
#define NN    64
#define RR    4
#define LL    4096
#define BBATCH 4

// Scratch (device globals: no runtime allocation allowed)
__device__ float g_P[(size_t)M_TOK * NFP];      // raw projections
__device__ float g_F[(size_t)M_TOK * NRF];      // H_new in (token, r*64+n) layout
__device__ float g_Wcat[(size_t)NFP * D_IN];    // packed weights
__device__ float g_bcat[NFP];                   // packed biases
__device__ float g_Hscratch[(size_t)BBATCH * RR * LL * NN]; // fallback H_new target

// ---------------------------------------------------------------------------
// Pack the four projection weight matrices + biases into one padded matrix.
// ---------------------------------------------------------------------------
__global__ void pack_kernel(const float* __restrict__ W_B, const float* __restrict__ b_B,
                            const float* __restrict__ W_X, const float* __restrict__ b_X,
                            const float* __restrict__ W_d, const float* __restrict__ b_d,
                            const float* __restrict__ W_t, const float* __restrict__ b_t) {
    int idx = blockIdx.x * blockDim.x + threadIdx.x;
    const int total = NFP * D_IN;
    for (int i = idx; i < total; i += gridDim.x * blockDim.x) {
        int f = i / D_IN, k = i - f * D_IN;
        float v = 0.f;
        if      (f < 256) v = W_B[f * D_IN + k];
        else if (f < 260) v = W_X[(f - 256) * D_IN + k];
        else if (f < 324) v = W_d[(f - 260) * D_IN + k];
        else if (f < 356) v = W_t[(f - 324) * D_IN + k];
        g_Wcat[i] = v;
    }
    if (idx < NFP) {
        float v = 0.f;
        if      (idx < 256) v = b_B[idx];
        else if (idx < 260) v = b_X[idx - 256];
        else if (idx < 324) v = b_d[idx - 260];
        else if (idx < 356) v = b_t[idx - 324];
        g_bcat[idx] = v;
    }
}

// ---------------------------------------------------------------------------
// Register-tiled SGEMM: C[m][n] = sum_k A[m*K+k] * B[n*K+k]  (+bias, +silu)
// BM=BN=128, BK=8, 256 threads, 8x8 micro-tile per thread.
// ---------------------------------------------------------------------------
template<bool SILU>
__global__ __launch_bounds__(256)
void sgemm_nt(const float* __restrict__ A, const float* __restrict__ Bm,
              const float* __restrict__ bias, float* __restrict__ C,
              int K, int ldc) {
    const int BM = 128, BN = 128, BK = 8, TM = 8, TN = 8;
    __shared__ float As[BK][BM];
    __shared__ float Bs[BK][BN];

    const int tid = threadIdx.x;
    const int m0 = blockIdx.x * BM;
    const int n0 = blockIdx.y * BN;

    const int lr = tid >> 1;            // 0..127: row within tile for loads
    const int lc = (tid & 1) * 4;       // 0 or 4: k-offset group

    const int tr = (tid >> 4) * TM;     // 0..120
    const int tc = (tid & 15) * TN;     // 0..120

    float acc[TM][TN];
    #pragma unroll
    for (int i = 0; i < TM; i++)
        #pragma unroll
        for (int j = 0; j < TN; j++) acc[i][j] = 0.f;

    for (int k0 = 0; k0 < K; k0 += BK) {
        float4 av = *reinterpret_cast<const float4*>(A + (size_t)(m0 + lr) * K + k0 + lc);
        float4 bv = *reinterpret_cast<const float4*>(Bm + (size_t)(n0 + lr) * K + k0 + lc);
        As[lc + 0][lr] = av.x; As[lc + 1][lr] = av.y;
        As[lc + 2][lr] = av.z; As[lc + 3][lr] = av.w;
        Bs[lc + 0][lr] = bv.x; Bs[lc + 1][lr] = bv.y;
        Bs[lc + 2][lr] = bv.z; Bs[lc + 3][lr] = bv.w;
        __syncthreads();

        #pragma unroll
        for (int kk = 0; kk < BK; kk++) {
            float af[TM], bf[TN];
            float4 a0 = *reinterpret_cast<const float4*>(&As[kk][tr]);
            float4 a1 = *reinterpret_cast<const float4*>(&As[kk][tr + 4]);
            float4 b0 = *reinterpret_cast<const float4*>(&Bs[kk][tc]);
            float4 b1 = *reinterpret_cast<const float4*>(&Bs[kk][tc + 4]);
            af[0]=a0.x; af[1]=a0.y; af[2]=a0.z; af[3]=a0.w;
            af[4]=a1.x; af[5]=a1.y; af[6]=a1.z; af[7]=a1.w;
            bf[0]=b0.x; bf[1]=b0.y; bf[2]=b0.z; bf[3]=b0.w;
            bf[4]=b1.x; bf[5]=b1.y; bf[6]=b1.z; bf[7]=b1.w;
            #pragma unroll
            for (int i = 0; i < TM; i++)
                #pragma unroll
                for (int j = 0; j < TN; j++)
                    acc[i][j] = fmaf(af[i], bf[j], acc[i][j]);
        }
        __syncthreads();
    }

    #pragma unroll
    for (int i = 0; i < TM; i++) {
        float* crow = C + (size_t)(m0 + tr + i) * ldc + n0 + tc;
        #pragma unroll
        for (int j = 0; j < TN; j++) {
            float v = acc[i][j];
            if (SILU) {
                v += bias[n0 + tc + j];
                v = v / (1.f + expf(-v));
            }
            crow[j] = v;
        }
    }
}

// ---------------------------------------------------------------------------
// Elementwise: silu/sigmoid/rotary/decay*H -> H_new (d_out) + flat (g_F)
// one block per token, 256 threads (thread t -> r = t/64, n = t%64)
// ---------------------------------------------------------------------------
__global__ __launch_bounds__(256)
void elementwise_kernel(const float* __restrict__ H, const int* __restrict__ layer_idx,
                        float* __restrict__ Hnew, float* __restrict__ F) {
    const int token = blockIdx.x;
    const int b = token >> 12;          // token / 4096
    const int l = token & 4095;
    const int t = threadIdx.x;

    __shared__ float sP[NF];
    __shared__ float sB[NRF];

    for (int i = t; i < NF; i += 256)
        sP[i] = g_P[(size_t)token * NFP + i] + g_bcat[i];
    __syncthreads();

    {   // silu of the 256 B-projection features
        float v = sP[t];
        sB[t] = v / (1.f + expf(-v));
    }
    __syncthreads();

    const int r = t >> 6;       // 0..3
    const int n = t & 63;       // 0..63
    const int j = n >> 1;       // rotary pair

    const float scale = (float)(*layer_idx + 1);
    const float th = sP[324 + j] * scale;
    float cs, sn;
    sincosf(th, &sn, &cs);

    const float x1 = sB[(n & ~1) * RR + r];
    const float x2 = sB[(n |  1) * RR + r];
    const float rot = (n & 1) ? (x1 * sn + x2 * cs) : (x1 * cs - x2 * sn);

    float xv = sP[256 + r];
    const float Xr = xv / (1.f + expf(-xv));

    float dv = sP[260 + n];
    const float decay = 1.f / (1.f + expf(-dv));

    const size_t hidx = (((size_t)(b * RR + r) * LL + l) * NN) + n;
    const float hnew = decay * H[hidx] + rot * Xr;

    Hnew[hidx] = hnew;
    F[(size_t)token * NRF + (r * NN + n)] = hnew;
}

// ---------------------------------------------------------------------------
extern "C" void kernel_launch(void* const* d_in, const int* in_sizes, int n_in,
                              void* d_out, int out_size) {
    const float* x       = (const float*)d_in[0];
    const float* H       = (const float*)d_in[1];
    const float* W_B     = (const float*)d_in[2];
    const float* b_B     = (const float*)d_in[3];
    const float* W_X     = (const float*)d_in[4];
    const float* b_X     = (const float*)d_in[5];
    const float* W_d     = (const float*)d_in[6];
    const float* b_d     = (const float*)d_in[7];
    const float* W_t     = (const float*)d_in[8];
    const float* b_t     = (const float*)d_in[9];
    const float* W_out   = (const float*)d_in[10];
    const float* b_out   = (const float*)d_in[11];
    const int*   lidx    = (const int*)d_in[12];

    const size_t HE = (size_t)BBATCH * RR * LL * NN;   //  4,194,304
    const size_t OE = (size_t)BBATCH * LL * D_IN;      // 16,777,216

    float* hnew_dst;
    float* out_dst;
    if ((size_t)out_size >= HE + OE) {
        hnew_dst = (float*)d_out;               // tuple concat: H_new then out
        out_dst  = (float*)d_out + HE;
    } else {                                    // fallback: only `out` expected
        cudaGetSymbolAddress((void**)&hnew_dst, g_Hscratch);
        out_dst  = (float*)d_out;
    }

    float *P_ptr, *F_ptr, *Wcat_ptr;
    cudaGetSymbolAddress((void**)&P_ptr,    g_P);
    cudaGetSymbolAddress((void**)&F_ptr,    g_F);
    cudaGetSymbolAddress((void**)&Wcat_ptr, g_Wcat);

    // 1) pack weights
    pack_kernel<<<768, 512>>>(W_B, b_B, W_X, b_X, W_d, b_d, W_t, b_t);

    // 2) projection GEMM: P[16384 x 384] = x @ Wcat^T
    {
        dim3 grid(M_TOK / 128, NFP / 128);
        sgemm_nt<false><<<grid, 256>>>(x, Wcat_ptr, nullptr, P_ptr, D_IN, NFP);
    }

    // 3) elementwise -> H_new + flat
    elementwise_kernel<<<M_TOK, 256>>>(H, lidx, hnew_dst, F_ptr);

    // 4) output GEMM: out[16384 x 1024] = silu(F @ W_out^T + b_out)
    {
        dim3 grid(M_TOK / 128, D_IN / 128);
        sgemm_nt<true><<<grid, 256>>>(F_ptr, W_out, b_out, out_dst, NRF, D_IN);
    }
}

// round 6
// speedup vs baseline: 2.3113x; 2.3113x over previous
#include <cuda_runtime.h>
#include <cuda_bf16.h>
#include <math.h>
#include <stdint.h>

// Problem constants
#define M_TOK 16384      // BATCH * L
#define D_IN  1024
#define NF    356        // 256 (B) + 4 (X) + 64 (decay) + 32 (theta)
#define NFP   384        // padded feature count
#define NRF   256        // N * R
#define NN    64
#define RR    4
#define LL    4096
#define BBATCH 4

// ---------------------------------------------------------------------------
// Scratch (device globals: no runtime allocation allowed)
// ---------------------------------------------------------------------------
__device__ __nv_bfloat16 g_xhi[(size_t)M_TOK * D_IN];
__device__ __nv_bfloat16 g_xlo[(size_t)M_TOK * D_IN];
__device__ __nv_bfloat16 g_Whi[(size_t)NFP * D_IN];
__device__ __nv_bfloat16 g_Wlo[(size_t)NFP * D_IN];
__device__ __nv_bfloat16 g_Fhi[(size_t)M_TOK * NRF];
__device__ __nv_bfloat16 g_Flo[(size_t)M_TOK * NRF];
__device__ __nv_bfloat16 g_Wohi[(size_t)D_IN * NRF];
__device__ __nv_bfloat16 g_Wolo[(size_t)D_IN * NRF];
__device__ float g_P[(size_t)M_TOK * NFP];
__device__ float g_bcat[NFP];
__device__ float g_Hscratch[(size_t)BBATCH * RR * LL * NN];

// ---------------------------------------------------------------------------
// PTX helpers (base sm_103 target: mma.sync + ldmatrix + cp.async only)
// ---------------------------------------------------------------------------
__device__ __forceinline__ uint32_t smem_u32(const void* p) {
    uint32_t a;
    asm("{ .reg .u64 t; cvta.to.shared.u64 t, %1; cvt.u32.u64 %0, t; }" : "=r"(a) : "l"(p));
    return a;
}

#define CP_ASYNC16(saddr, gptr) \
    asm volatile("cp.async.cg.shared.global [%0], [%1], 16;" :: "r"(saddr), "l"(gptr) : "memory")
#define CP_COMMIT() asm volatile("cp.async.commit_group;" ::: "memory")
#define CP_WAIT(n)  asm volatile("cp.async.wait_group " #n ";" ::: "memory")

__device__ __forceinline__ void ldm_x4(uint32_t* r, uint32_t addr) {
    asm volatile("ldmatrix.sync.aligned.m8n8.x4.shared.b16 {%0,%1,%2,%3}, [%4];"
                 : "=r"(r[0]), "=r"(r[1]), "=r"(r[2]), "=r"(r[3]) : "r"(addr));
}
__device__ __forceinline__ void ldm_x2(uint32_t* r, uint32_t addr) {
    asm volatile("ldmatrix.sync.aligned.m8n8.x2.shared.b16 {%0,%1}, [%2];"
                 : "=r"(r[0]), "=r"(r[1]) : "r"(addr));
}
__device__ __forceinline__ void mma16816(float* c, const uint32_t* a, const uint32_t* b) {
    asm volatile(
        "mma.sync.aligned.m16n8k16.row.col.f32.bf16.bf16.f32 "
        "{%0,%1,%2,%3}, {%4,%5,%6,%7}, {%8,%9}, {%0,%1,%2,%3};"
        : "+f"(c[0]), "+f"(c[1]), "+f"(c[2]), "+f"(c[3])
        : "r"(a[0]), "r"(a[1]), "r"(a[2]), "r"(a[3]), "r"(b[0]), "r"(b[1]));
}

// ---------------------------------------------------------------------------
// Split fp32 -> (hi, lo) bf16
// ---------------------------------------------------------------------------
__global__ void split_kernel(const float* __restrict__ src,
                             __nv_bfloat16* __restrict__ hi,
                             __nv_bfloat16* __restrict__ lo, int n4) {
    int i = blockIdx.x * blockDim.x + threadIdx.x;
    if (i >= n4) return;
    float4 v = reinterpret_cast<const float4*>(src)[i];
    __nv_bfloat16 h0 = __float2bfloat16(v.x), h1 = __float2bfloat16(v.y);
    __nv_bfloat16 h2 = __float2bfloat16(v.z), h3 = __float2bfloat16(v.w);
    __nv_bfloat162 H01; H01.x = h0; H01.y = h1;
    __nv_bfloat162 H23; H23.x = h2; H23.y = h3;
    __nv_bfloat162 L01, L23;
    L01.x = __float2bfloat16(v.x - __bfloat162float(h0));
    L01.y = __float2bfloat16(v.y - __bfloat162float(h1));
    L23.x = __float2bfloat16(v.z - __bfloat162float(h2));
    L23.y = __float2bfloat16(v.w - __bfloat162float(h3));
    reinterpret_cast<__nv_bfloat162*>(hi)[2 * i]     = H01;
    reinterpret_cast<__nv_bfloat162*>(hi)[2 * i + 1] = H23;
    reinterpret_cast<__nv_bfloat162*>(lo)[2 * i]     = L01;
    reinterpret_cast<__nv_bfloat162*>(lo)[2 * i + 1] = L23;
}

// ---------------------------------------------------------------------------
// Pack + split the four projection weight matrices into g_Whi/g_Wlo + g_bcat
// ---------------------------------------------------------------------------
__global__ void pack_split_kernel(const float* __restrict__ W_B, const float* __restrict__ b_B,
                                  const float* __restrict__ W_X, const float* __restrict__ b_X,
                                  const float* __restrict__ W_d, const float* __restrict__ b_d,
                                  const float* __restrict__ W_t, const float* __restrict__ b_t) {
    int idx = blockIdx.x * blockDim.x + threadIdx.x;
    const int total = NFP * D_IN;
    for (int i = idx; i < total; i += gridDim.x * blockDim.x) {
        int f = i >> 10, k = i & 1023;
        float v = 0.f;
        if      (f < 256) v = W_B[f * D_IN + k];
        else if (f < 260) v = W_X[(f - 256) * D_IN + k];
        else if (f < 324) v = W_d[(f - 260) * D_IN + k];
        else if (f < 356) v = W_t[(f - 324) * D_IN + k];
        __nv_bfloat16 h = __float2bfloat16(v);
        g_Whi[i] = h;
        g_Wlo[i] = __float2bfloat16(v - __bfloat162float(h));
    }
    if (idx < NFP) {
        float v = 0.f;
        if      (idx < 256) v = b_B[idx];
        else if (idx < 260) v = b_X[idx - 256];
        else if (idx < 324) v = b_d[idx - 260];
        else if (idx < 356) v = b_t[idx - 324];
        g_bcat[idx] = v;
    }
}

// ---------------------------------------------------------------------------
// HMMA split-bf16 GEMM: C[m][n] = sum_k A[m,k]*B[n,k]
// 3-term: Ahi*Bhi + Ahi*Blo + Alo*Bhi.  Tile 128x128, BK=32, 256 threads.
// cp.async 2-stage double buffer; rows padded to 40 bf16 (80B) -> ldmatrix
// conflict-free. Warp grid 2(M) x 4(N), warp tile 64x32.
// ---------------------------------------------------------------------------
#define ROWB 80                       // padded row stride in bytes (40 bf16)
#define TILEB (128 * ROWB)            // 10240 bytes per (matrix, half)
#define STAGEB (4 * TILEB)            // Ahi, Alo, Bhi, Blo = 40960 bytes

template<bool SILU>
__global__ __launch_bounds__(256, 1)
void mma_gemm(const __nv_bfloat16* __restrict__ Ahi, const __nv_bfloat16* __restrict__ Alo,
              const __nv_bfloat16* __restrict__ Bhi, const __nv_bfloat16* __restrict__ Blo,
              const float* __restrict__ bias, float* __restrict__ C, int K, int ldc) {
    extern __shared__ __align__(128) char smem[];
    const uint32_t sb = smem_u32(smem);

    const int tid = threadIdx.x;
    const int wid = tid >> 5, lane = tid & 31;
    const int wm = wid & 1;            // 0..1  (M)
    const int wn = wid >> 1;           // 0..3  (N)
    const int m0 = blockIdx.x * 128, n0 = blockIdx.y * 128;

    // cp.async per-thread chunk coords: 512 16B-chunks per (matrix,half) per stage
    // thread handles chunks tid and tid+256: row = c>>2, kchunk = c&3
    const int c0r = tid >> 2,        c0k = tid & 3;
    const int c1r = (tid + 256) >> 2, c1k = tid & 3;  // (tid+256)&3 == tid&3

    // ldmatrix lane addressing (byte offsets within a tile)
    const int a_row = (lane & 7) + ((lane >> 3) & 1) * 8;  // 0..15
    const int a_kc  = lane >> 4;                           // 0..1 (k chunk of 8)
    const uint32_t a_base = (uint32_t)((wm * 64 + a_row) * ROWB + a_kc * 16);
    const int b_row = lane & 7;
    const int b_kc  = (lane >> 3) & 1;
    const uint32_t b_base = (uint32_t)((wn * 32 + b_row) * ROWB + b_kc * 16);

    float acc[4][4][4];
    #pragma unroll
    for (int i = 0; i < 4; i++)
        #pragma unroll
        for (int j = 0; j < 4; j++)
            #pragma unroll
            for (int q = 0; q < 4; q++) acc[i][j][q] = 0.f;

    const int nkb = K >> 5;

    // stage loader (all 256 threads): 8 cp.asyncs each
    auto load_stage = [&](int kb, int stage) {
        const uint32_t s0 = sb + stage * STAGEB;
        const int kofs = kb << 5;  // k offset in elements
        {   // chunk set 0
            size_t ga = (size_t)(m0 + c0r) * K + kofs + c0k * 8;
            size_t gb = (size_t)(n0 + c0r) * K + kofs + c0k * 8;
            uint32_t so = (uint32_t)(c0r * ROWB + c0k * 16);
            CP_ASYNC16(s0 + 0 * TILEB + so, Ahi + ga);
            CP_ASYNC16(s0 + 1 * TILEB + so, Alo + ga);
            CP_ASYNC16(s0 + 2 * TILEB + so, Bhi + gb);
            CP_ASYNC16(s0 + 3 * TILEB + so, Blo + gb);
        }
        {   // chunk set 1
            size_t ga = (size_t)(m0 + c1r) * K + kofs + c1k * 8;
            size_t gb = (size_t)(n0 + c1r) * K + kofs + c1k * 8;
            uint32_t so = (uint32_t)(c1r * ROWB + c1k * 16);
            CP_ASYNC16(s0 + 0 * TILEB + so, Ahi + ga);
            CP_ASYNC16(s0 + 1 * TILEB + so, Alo + ga);
            CP_ASYNC16(s0 + 2 * TILEB + so, Bhi + gb);
            CP_ASYNC16(s0 + 3 * TILEB + so, Blo + gb);
        }
    };

    load_stage(0, 0);
    CP_COMMIT();

    int buf = 0;
    for (int kb = 0; kb < nkb; kb++) {
        if (kb + 1 < nkb) {
            load_stage(kb + 1, buf ^ 1);
            CP_COMMIT();
            CP_WAIT(1);
        } else {
            CP_WAIT(0);
        }
        __syncthreads();

        const uint32_t s0 = sb + buf * STAGEB;
        #pragma unroll
        for (int s = 0; s < 2; s++) {          // two k16 steps per BK=32
            uint32_t ah[4][4], al[4][4], bh[4][2], bl[4][2];
            #pragma unroll
            for (int i = 0; i < 4; i++) {
                uint32_t ao = s0 + a_base + (uint32_t)(i * 16 * ROWB + s * 32);
                ldm_x4(ah[i], ao);               // Ahi tile
                ldm_x4(al[i], ao + TILEB);       // Alo tile
            }
            #pragma unroll
            for (int j = 0; j < 4; j++) {
                uint32_t bo = s0 + 2 * TILEB + b_base + (uint32_t)(j * 8 * ROWB + s * 32);
                ldm_x2(bh[j], bo);               // Bhi tile
                ldm_x2(bl[j], bo + TILEB);       // Blo tile
            }
            #pragma unroll
            for (int i = 0; i < 4; i++)
                #pragma unroll
                for (int j = 0; j < 4; j++) {
                    mma16816(acc[i][j], ah[i], bh[j]);
                    mma16816(acc[i][j], ah[i], bl[j]);
                    mma16816(acc[i][j], al[i], bh[j]);
                }
        }
        __syncthreads();
        buf ^= 1;
    }

    // Epilogue
    const int tr = lane >> 2;            // 0..7
    const int tc = (lane & 3) * 2;       // 0,2,4,6
    #pragma unroll
    for (int i = 0; i < 4; i++) {
        #pragma unroll
        for (int j = 0; j < 4; j++) {
            int m = m0 + wm * 64 + i * 16 + tr;
            int n = n0 + wn * 32 + j * 8 + tc;
            float e0 = acc[i][j][0], e1 = acc[i][j][1];
            float e2 = acc[i][j][2], e3 = acc[i][j][3];
            if (SILU) {
                float bb0 = bias[n], bb1 = bias[n + 1];
                e0 += bb0; e1 += bb1; e2 += bb0; e3 += bb1;
                e0 = e0 / (1.f + __expf(-e0));
                e1 = e1 / (1.f + __expf(-e1));
                e2 = e2 / (1.f + __expf(-e2));
                e3 = e3 / (1.f + __expf(-e3));
            }
            float2* p0 = reinterpret_cast<float2*>(C + (size_t)m * ldc + n);
            float2* p1 = reinterpret_cast<float2*>(C + (size_t)(m + 8) * ldc + n);
            *p0 = make_float2(e0, e1);
            *p1 = make_float2(e2, e3);
        }
    }
}

// ---------------------------------------------------------------------------
// Elementwise: silu/sigmoid/rotary/decay*H -> H_new (fp32) + F split (bf16 hi/lo)
// ---------------------------------------------------------------------------
__global__ __launch_bounds__(256)
void elementwise_kernel(const float* __restrict__ H, const int* __restrict__ layer_idx,
                        float* __restrict__ Hnew,
                        __nv_bfloat16* __restrict__ Fhi, __nv_bfloat16* __restrict__ Flo) {
    const int token = blockIdx.x;
    const int b = token >> 12;
    const int l = token & 4095;
    const int t = threadIdx.x;

    __shared__ float sP[NF];
    __shared__ float sB[NRF];

    for (int i = t; i < NF; i += 256)
        sP[i] = g_P[(size_t)token * NFP + i] + g_bcat[i];
    __syncthreads();

    {
        float v = sP[t];
        sB[t] = v / (1.f + __expf(-v));
    }
    __syncthreads();

    const int r = t >> 6;
    const int n = t & 63;
    const int j = n >> 1;

    const float scale = (float)(*layer_idx + 1);
    const float th = sP[324 + j] * scale;
    float cs, sn;
    sincosf(th, &sn, &cs);

    const float x1 = sB[(n & ~1) * RR + r];
    const float x2 = sB[(n |  1) * RR + r];
    const float rot = (n & 1) ? (x1 * sn + x2 * cs) : (x1 * cs - x2 * sn);

    float xv = sP[256 + r];
    const float Xr = xv / (1.f + __expf(-xv));

    float dv = sP[260 + n];
    const float decay = 1.f / (1.f + __expf(-dv));

    const size_t hidx = (((size_t)(b * RR + r) * LL + l) * NN) + n;
    const float hnew = decay * H[hidx] + rot * Xr;

    Hnew[hidx] = hnew;

    __nv_bfloat16 h = __float2bfloat16(hnew);
    const size_t fidx = (size_t)token * NRF + (r * NN + n);
    Fhi[fidx] = h;
    Flo[fidx] = __float2bfloat16(hnew - __bfloat162float(h));
}

// ---------------------------------------------------------------------------
extern "C" void kernel_launch(void* const* d_in, const int* in_sizes, int n_in,
                              void* d_out, int out_size) {
    const float* x     = (const float*)d_in[0];
    const float* H     = (const float*)d_in[1];
    const float* W_B   = (const float*)d_in[2];
    const float* b_B   = (const float*)d_in[3];
    const float* W_X   = (const float*)d_in[4];
    const float* b_X   = (const float*)d_in[5];
    const float* W_d   = (const float*)d_in[6];
    const float* b_d   = (const float*)d_in[7];
    const float* W_t   = (const float*)d_in[8];
    const float* b_t   = (const float*)d_in[9];
    const float* W_out = (const float*)d_in[10];
    const float* b_out = (const float*)d_in[11];
    const int*   lidx  = (const int*)d_in[12];

    const size_t HE = (size_t)BBATCH * RR * LL * NN;   //  4,194,304
    const size_t OE = (size_t)BBATCH * LL * D_IN;      // 16,777,216

    float* hnew_dst;
    float* out_dst;
    if ((size_t)out_size >= HE + OE) {
        hnew_dst = (float*)d_out;
        out_dst  = (float*)d_out + HE;
    } else {
        cudaGetSymbolAddress((void**)&hnew_dst, g_Hscratch);
        out_dst  = (float*)d_out;
    }

    __nv_bfloat16 *xhi, *xlo, *Whi, *Wlo, *Fhi, *Flo, *Wohi, *Wolo;
    float* P_ptr;
    cudaGetSymbolAddress((void**)&xhi,  g_xhi);
    cudaGetSymbolAddress((void**)&xlo,  g_xlo);
    cudaGetSymbolAddress((void**)&Whi,  g_Whi);
    cudaGetSymbolAddress((void**)&Wlo,  g_Wlo);
    cudaGetSymbolAddress((void**)&Fhi,  g_Fhi);
    cudaGetSymbolAddress((void**)&Flo,  g_Flo);
    cudaGetSymbolAddress((void**)&Wohi, g_Wohi);
    cudaGetSymbolAddress((void**)&Wolo, g_Wolo);
    cudaGetSymbolAddress((void**)&P_ptr, g_P);

    const int SMEM_BYTES = 2 * STAGEB;  // 81920
    cudaFuncSetAttribute(mma_gemm<false>, cudaFuncAttributeMaxDynamicSharedMemorySize, SMEM_BYTES);
    cudaFuncSetAttribute(mma_gemm<true>,  cudaFuncAttributeMaxDynamicSharedMemorySize, SMEM_BYTES);

    // 1) conversions / packing
    {
        int n4 = M_TOK * D_IN / 4;
        split_kernel<<<(n4 + 255) / 256, 256>>>(x, xhi, xlo, n4);
    }
    pack_split_kernel<<<768, 512>>>(W_B, b_B, W_X, b_X, W_d, b_d, W_t, b_t);
    {
        int n4 = D_IN * NRF / 4;
        split_kernel<<<(n4 + 255) / 256, 256>>>(W_out, Wohi, Wolo, n4);
    }

    // 2) projection GEMM: P[16384 x 384] = x @ Wcat^T  (HMMA split-bf16)
    mma_gemm<false><<<dim3(M_TOK / 128, NFP / 128), 256, SMEM_BYTES>>>(
        xhi, xlo, Whi, Wlo, nullptr, P_ptr, D_IN, NFP);

    // 3) elementwise -> H_new + F split
    elementwise_kernel<<<M_TOK, 256>>>(H, lidx, hnew_dst, Fhi, Flo);

    // 4) output GEMM: out[16384 x 1024] = silu(F @ W_out^T + b_out)
    mma_gemm<true><<<dim3(M_TOK / 128, D_IN / 128), 256, SMEM_BYTES>>>(
        Fhi, Flo, Wohi, Wolo, b_out, out_dst, NRF, D_IN);
}